// round 12
// baseline (speedup 1.0000x reference)
#include <cuda_runtime.h>
#include <cuda_bf16.h>
#include <math.h>
#include <stdint.h>

// Problem constants
#define BB 32
#define TT 2048
#define EE 1024
#define AA 1024
#define DD 1024
#define MROWS (BB * TT)   // 65536

// ---------------------------------------------------------------------------
// Scratch (__device__ globals; no cudaMalloc allowed)
// ---------------------------------------------------------------------------
__device__ __nv_bfloat16 g_encsplit[(size_t)MROWS * 2048]; // [row, 0:1024]=hi, [1024:2048]=lo
__device__ __nv_bfloat16 g_wsplit[(size_t)AA * 2048];      // [a, 0:1024]=W^T hi, [1024:2048]=lo
__device__ float g_dp[BB * AA];                            // dec_proj + b_enc
__device__ float g_energy[BB * TT];                        // pre-softmax energy

// ---------------------------------------------------------------------------
// PTX helpers (base-target-safe only: cp.async / ldmatrix / mma.sync)
// ---------------------------------------------------------------------------
__device__ __forceinline__ uint32_t smem_u32(const void* p) {
    uint32_t a;
    asm("{ .reg .u64 t; cvta.to.shared.u64 t, %1; cvt.u32.u64 %0, t; }" : "=r"(a) : "l"(p));
    return a;
}

__device__ __forceinline__ void cp_async16(uint32_t dst, const void* src) {
    asm volatile("cp.async.cg.shared.global [%0], [%1], 16;\n" :: "r"(dst), "l"(src));
}
#define CP_COMMIT() asm volatile("cp.async.commit_group;\n" ::: "memory")
#define CP_WAIT1()  asm volatile("cp.async.wait_group 1;\n" ::: "memory")
#define CP_WAIT0()  asm volatile("cp.async.wait_group 0;\n" ::: "memory")

__device__ __forceinline__ void ldm_x4(uint32_t& r0, uint32_t& r1, uint32_t& r2, uint32_t& r3,
                                       uint32_t addr) {
    asm volatile("ldmatrix.sync.aligned.m8n8.x4.shared.b16 {%0,%1,%2,%3}, [%4];"
                 : "=r"(r0), "=r"(r1), "=r"(r2), "=r"(r3) : "r"(addr));
}

__device__ __forceinline__ void mma_bf16(float* c, uint32_t a0, uint32_t a1, uint32_t a2,
                                         uint32_t a3, uint32_t b0, uint32_t b1) {
    asm volatile(
        "mma.sync.aligned.m16n8k16.row.col.f32.bf16.bf16.f32 "
        "{%0,%1,%2,%3}, {%4,%5,%6,%7}, {%8,%9}, {%0,%1,%2,%3};"
        : "+f"(c[0]), "+f"(c[1]), "+f"(c[2]), "+f"(c[3])
        : "r"(a0), "r"(a1), "r"(a2), "r"(a3), "r"(b0), "r"(b1));
}

// ---------------------------------------------------------------------------
// 0) zero energy + ctx; seed dp with b_enc
// ---------------------------------------------------------------------------
__global__ void zero_kernel(float* __restrict__ energy, float* __restrict__ ctx,
                            float* __restrict__ dp, const float* __restrict__ b_enc) {
    int i = blockIdx.x * blockDim.x + threadIdx.x;
    if (i < BB * TT) energy[i] = 0.0f;
    if (i < BB * EE) ctx[i] = 0.0f;
    if (i < BB * AA) dp[i] = b_enc[i & (AA - 1)];
}

// ---------------------------------------------------------------------------
// 1) split enc_out into bf16 hi/lo
// ---------------------------------------------------------------------------
__global__ void split_enc_kernel(const float* __restrict__ enc) {
    int row = blockIdx.x;
    int tid = threadIdx.x;  // 0..255
    float4 x = ((const float4*)(enc + (size_t)row * EE))[tid];
    union { __nv_bfloat16 h[4]; uint2 u; } hi, lo;
    float xs[4] = {x.x, x.y, x.z, x.w};
    #pragma unroll
    for (int k = 0; k < 4; k++) {
        __nv_bfloat16 h = __float2bfloat16(xs[k]);
        hi.h[k] = h;
        lo.h[k] = __float2bfloat16(xs[k] - __bfloat162float(h));
    }
    __nv_bfloat16* base = g_encsplit + (size_t)row * 2048;
    *(uint2*)(base + tid * 4)        = hi.u;
    *(uint2*)(base + 1024 + tid * 4) = lo.u;
}

// ---------------------------------------------------------------------------
// 2) split + transpose W_enc: g_wsplit[a, e] = bf16split(W_enc[e, a])
// ---------------------------------------------------------------------------
__global__ void split_w_kernel(const float* __restrict__ W) {
    __shared__ float tile[32][33];
    int e0 = blockIdx.x * 32, a0 = blockIdx.y * 32;
    int tx = threadIdx.x, ty = threadIdx.y;  // 32 x 8
    #pragma unroll
    for (int k = 0; k < 4; k++) {
        int e = ty + k * 8;
        tile[e][tx] = W[(size_t)(e0 + e) * AA + a0 + tx];
    }
    __syncthreads();
    #pragma unroll
    for (int k = 0; k < 4; k++) {
        int a = ty + k * 8;
        float val = tile[tx][a];
        __nv_bfloat16 h = __float2bfloat16(val);
        __nv_bfloat16 l = __float2bfloat16(val - __bfloat162float(h));
        __nv_bfloat16* base = g_wsplit + (size_t)(a0 + a) * 2048;
        base[e0 + tx] = h;
        base[1024 + e0 + tx] = l;
    }
}

// ---------------------------------------------------------------------------
// 3) dec_proj: dp[b,a] += sum_d dec[b,d] * W_dec[d,a]   (dp pre-seeded b_enc)
// ---------------------------------------------------------------------------
__global__ void dec_proj_kernel(const float* __restrict__ dec,
                                const float* __restrict__ Wdec,
                                float* __restrict__ dp) {
    int a0 = blockIdx.x * 128;
    int d0 = blockIdx.y * 32;
    __shared__ float wsm[32][128];
    __shared__ float dsm[32][32];
    int tid = threadIdx.x;
    for (int i = tid; i < 32 * 128; i += 256) {
        int d = i >> 7, a = i & 127;
        wsm[d][a] = Wdec[(size_t)(d0 + d) * AA + a0 + a];
    }
    for (int i = tid; i < 32 * 32; i += 256) {
        int b = i >> 5, d = i & 31;
        dsm[b][d] = dec[b * DD + d0 + d];
    }
    __syncthreads();
    int a = tid & 127;
    int b0 = (tid >> 7) * 16;
    #pragma unroll
    for (int bi = 0; bi < 16; bi++) {
        int b = b0 + bi;
        float s = 0.0f;
        #pragma unroll
        for (int d = 0; d < 32; d++)
            s = fmaf(dsm[b][d], wsm[d][a], s);
        atomicAdd(&dp[b * AA + a0 + a], s);
    }
}

// ---------------------------------------------------------------------------
// 4) mma.sync bf16-split GEMM + tanh + v-dot -> energy
//    CTA 128x256, 8 warps (2 row-groups x 4 col-groups), warp tile 64x64.
//    Real-K slabs of 32; per stage {A_hi, A_lo (128x32), B_hi, B_lo (256x32)}.
//    Products: A_hi*B_hi + A_hi*B_lo + A_lo*B_hi (A frags reloaded for lo).
// ---------------------------------------------------------------------------
#define ROWB 80                    // padded smem row stride (bytes) for 32 bf16
#define A_TILE (128 * ROWB)        // 10240
#define B_TILE (256 * ROWB)        // 20480
#define STG (2 * A_TILE + 2 * B_TILE)   // 61440
#define GEMM_SMEM (2 * STG)        // 122880
#define NCHUNK 32

__device__ __forceinline__ void load_stage(int chunk, uint32_t st,
                                           int rowBase, int colBase, int tid) {
    const char* aHi = (const char*)g_encsplit + (size_t)rowBase * 4096 + (size_t)chunk * 64;
    const char* bHi = (const char*)g_wsplit  + (size_t)colBase * 4096 + (size_t)chunk * 64;
    // A_hi, A_lo: 128 rows x 4 segs of 16B each
    #pragma unroll
    for (int t4 = 0; t4 < 2; t4++) {
        const char* src = aHi + t4 * 2048;
        uint32_t dstBase = st + t4 * A_TILE;
        #pragma unroll
        for (int k = 0; k < 2; k++) {
            int idx = tid + k * 256;
            int r = idx >> 2, sg = idx & 3;
            cp_async16(dstBase + r * ROWB + sg * 16, src + (size_t)r * 4096 + sg * 16);
        }
    }
    // B_hi, B_lo: 256 rows x 4 segs of 16B each
    #pragma unroll
    for (int t4 = 0; t4 < 2; t4++) {
        const char* src = bHi + t4 * 2048;
        uint32_t dstBase = st + 2 * A_TILE + t4 * B_TILE;
        #pragma unroll
        for (int k = 0; k < 4; k++) {
            int idx = tid + k * 256;
            int r = idx >> 2, sg = idx & 3;
            cp_async16(dstBase + r * ROWB + sg * 16, src + (size_t)r * 4096 + sg * 16);
        }
    }
}

__global__ __launch_bounds__(256, 1)
void energy_gemm_mma(const float* __restrict__ dp,
                     const float* __restrict__ v,
                     float* __restrict__ energy) {
    extern __shared__ char smem[];
    uint32_t sb = smem_u32(smem);
    int tid = threadIdx.x;
    int lane = tid & 31;
    int w = tid >> 5;
    int wm = w >> 2;          // 0..1  (64 rows each)
    int wn = w & 3;           // 0..3  (64 cols each)
    int rowBase = blockIdx.y * 128;
    int colBase = blockIdx.x * 256;
    int b = rowBase >> 11;

    float acc[4][8][4];       // [mt 16-rows][nt 8-cols][reg] = 128 regs
    #pragma unroll
    for (int i = 0; i < 4; i++)
        #pragma unroll
        for (int jj = 0; jj < 8; jj++)
            #pragma unroll
            for (int r = 0; r < 4; r++) acc[i][jj][r] = 0.0f;

    load_stage(0, sb, rowBase, colBase, tid);
    CP_COMMIT();
    load_stage(1, sb + STG, rowBase, colBase, tid);
    CP_COMMIT();

    // ldmatrix base offsets (relative to tile base)
    uint32_t aAddrOff = (uint32_t)((wm * 64 + (lane & 15)) * ROWB + ((lane >> 4) & 1) * 16);
    uint32_t bAddrOff = (uint32_t)((wn * 64 + (lane & 7) + ((lane >> 4) & 1) * 8) * ROWB
                                   + ((lane >> 3) & 1) * 16);

    for (int i = 0; i < NCHUNK; i++) {
        if (i < NCHUNK - 1) CP_WAIT1(); else CP_WAIT0();
        __syncthreads();
        uint32_t st = sb + (i & 1) * STG;
        uint32_t Ahi = st;
        uint32_t Alo = st + A_TILE;
        uint32_t Bhi = st + 2 * A_TILE;
        uint32_t Blo = Bhi + B_TILE;

        #pragma unroll
        for (int ks = 0; ks < 2; ks++) {
            uint32_t af[4][4];
            uint32_t bh[4][4], bl[4][4];   // 4 n-pairs x 16 cols
            #pragma unroll
            for (int mt = 0; mt < 4; mt++)
                ldm_x4(af[mt][0], af[mt][1], af[mt][2], af[mt][3],
                       Ahi + aAddrOff + mt * 16 * ROWB + ks * 32);
            #pragma unroll
            for (int np = 0; np < 4; np++)
                ldm_x4(bh[np][0], bh[np][1], bh[np][2], bh[np][3],
                       Bhi + bAddrOff + np * 16 * ROWB + ks * 32);
            #pragma unroll
            for (int np = 0; np < 4; np++)
                ldm_x4(bl[np][0], bl[np][1], bl[np][2], bl[np][3],
                       Blo + bAddrOff + np * 16 * ROWB + ks * 32);
            // A_hi * B_hi
            #pragma unroll
            for (int mt = 0; mt < 4; mt++)
                #pragma unroll
                for (int nt = 0; nt < 8; nt++)
                    mma_bf16(acc[mt][nt], af[mt][0], af[mt][1], af[mt][2], af[mt][3],
                             bh[nt >> 1][(nt & 1) * 2 + 0], bh[nt >> 1][(nt & 1) * 2 + 1]);
            // A_hi * B_lo
            #pragma unroll
            for (int mt = 0; mt < 4; mt++)
                #pragma unroll
                for (int nt = 0; nt < 8; nt++)
                    mma_bf16(acc[mt][nt], af[mt][0], af[mt][1], af[mt][2], af[mt][3],
                             bl[nt >> 1][(nt & 1) * 2 + 0], bl[nt >> 1][(nt & 1) * 2 + 1]);
            // A_lo * B_hi  (reuse af registers)
            #pragma unroll
            for (int mt = 0; mt < 4; mt++)
                ldm_x4(af[mt][0], af[mt][1], af[mt][2], af[mt][3],
                       Alo + aAddrOff + mt * 16 * ROWB + ks * 32);
            #pragma unroll
            for (int mt = 0; mt < 4; mt++)
                #pragma unroll
                for (int nt = 0; nt < 8; nt++)
                    mma_bf16(acc[mt][nt], af[mt][0], af[mt][1], af[mt][2], af[mt][3],
                             bh[nt >> 1][(nt & 1) * 2 + 0], bh[nt >> 1][(nt & 1) * 2 + 1]);
        }
        __syncthreads();
        if (i + 2 < NCHUNK) {
            load_stage(i + 2, st, rowBase, colBase, tid);
            CP_COMMIT();
        }
    }
    __syncthreads();

    // Epilogue: s[row] = sum_col v[col] * tanh(acc + dp[col]); quad shfl-reduce
    float* red = (float*)smem;    // [128][4]
    #pragma unroll
    for (int mt = 0; mt < 4; mt++) {
        float s0 = 0.0f, s1 = 0.0f;
        #pragma unroll
        for (int nt = 0; nt < 8; nt++) {
            int col = colBase + wn * 64 + nt * 8 + (lane & 3) * 2;
            float d0 = dp[b * AA + col], d1 = dp[b * AA + col + 1];
            float v0 = v[col], v1 = v[col + 1];
            s0 = fmaf(v0, tanhf(acc[mt][nt][0] + d0), s0);
            s0 = fmaf(v1, tanhf(acc[mt][nt][1] + d1), s0);
            s1 = fmaf(v0, tanhf(acc[mt][nt][2] + d0), s1);
            s1 = fmaf(v1, tanhf(acc[mt][nt][3] + d1), s1);
        }
        s0 += __shfl_xor_sync(0xFFFFFFFF, s0, 1);
        s0 += __shfl_xor_sync(0xFFFFFFFF, s0, 2);
        s1 += __shfl_xor_sync(0xFFFFFFFF, s1, 1);
        s1 += __shfl_xor_sync(0xFFFFFFFF, s1, 2);
        if ((lane & 3) == 0) {
            int r0 = wm * 64 + mt * 16 + (lane >> 2);
            red[r0 * 4 + wn] = s0;
            red[(r0 + 8) * 4 + wn] = s1;
        }
    }
    __syncthreads();
    if (tid < 128) {
        float s = red[tid * 4] + red[tid * 4 + 1] + red[tid * 4 + 2] + red[tid * 4 + 3];
        atomicAdd(&energy[rowBase + tid], s);
    }
}

// ---------------------------------------------------------------------------
// 5) masked softmax per batch row (0/1 multiply-mask semantics)
// ---------------------------------------------------------------------------
__global__ void softmax_kernel(const float* __restrict__ energy,
                               const int* __restrict__ x_lens,
                               float* __restrict__ att) {
    int b = blockIdx.x;
    int tid = threadIdx.x;
    int len = x_lens[b];
    __shared__ float sh[256];

    float e[8];
    float mx = -1e30f;
    #pragma unroll
    for (int j = 0; j < 8; j++) {
        int t = tid + j * 256;
        float val = energy[b * TT + t];
        val = (t < len) ? val : 0.0f;
        e[j] = val;
        mx = fmaxf(mx, val);
    }
    sh[tid] = mx;
    __syncthreads();
    for (int s = 128; s > 0; s >>= 1) {
        if (tid < s) sh[tid] = fmaxf(sh[tid], sh[tid + s]);
        __syncthreads();
    }
    mx = sh[0];
    __syncthreads();

    float sum = 0.0f;
    #pragma unroll
    for (int j = 0; j < 8; j++) {
        e[j] = expf(e[j] - mx);
        sum += e[j];
    }
    sh[tid] = sum;
    __syncthreads();
    for (int s = 128; s > 0; s >>= 1) {
        if (tid < s) sh[tid] += sh[tid + s];
        __syncthreads();
    }
    float inv = 1.0f / sh[0];

    #pragma unroll
    for (int j = 0; j < 8; j++) {
        int t = tid + j * 256;
        att[b * TT + t] = e[j] * inv;
    }
}

// ---------------------------------------------------------------------------
// 6) context[b,e] = sum_t att[b,t] * enc[b,t,e]
// ---------------------------------------------------------------------------
__global__ void context_kernel(const float* __restrict__ enc,
                               const float* __restrict__ att,
                               float* __restrict__ ctx) {
    int b = blockIdx.x;
    int t0 = blockIdx.y * 128;
    int tid = threadIdx.x;

    __shared__ float ws[128];
    if (tid < 128) ws[tid] = att[b * TT + t0 + tid];
    __syncthreads();

    float acc[4] = {0.0f, 0.0f, 0.0f, 0.0f};
    for (int t = 0; t < 128; t++) {
        float w = ws[t];
        const float* row = enc + ((size_t)(b * TT + t0 + t)) * EE;
        #pragma unroll
        for (int j = 0; j < 4; j++)
            acc[j] = fmaf(w, row[tid + j * 256], acc[j]);
    }
    #pragma unroll
    for (int j = 0; j < 4; j++)
        atomicAdd(&ctx[b * EE + tid + j * 256], acc[j]);
}

// ---------------------------------------------------------------------------
// launch
// ---------------------------------------------------------------------------
extern "C" void kernel_launch(void* const* d_in, const int* in_sizes, int n_in,
                              void* d_out, int out_size) {
    const float* enc_out = (const float*)d_in[0];
    const int*   x_lens  = (const int*)  d_in[1];
    const float* dec_out = (const float*)d_in[2];
    const float* W_enc   = (const float*)d_in[4];
    const float* b_enc   = (const float*)d_in[5];
    const float* W_dec   = (const float*)d_in[6];
    const float* v       = (const float*)d_in[7];

    float* out = (float*)d_out;
    float* ctx = out;
    float* att = out + BB * EE;

    float* dp;
    float* energy;
    cudaGetSymbolAddress((void**)&dp, g_dp);
    cudaGetSymbolAddress((void**)&energy, g_energy);

    cudaFuncSetAttribute(energy_gemm_mma,
                         cudaFuncAttributeMaxDynamicSharedMemorySize, GEMM_SMEM);

    zero_kernel<<<(BB * TT + 255) / 256, 256>>>(energy, ctx, dp, b_enc);
    split_enc_kernel<<<MROWS, 256>>>(enc_out);
    split_w_kernel<<<dim3(32, 32), dim3(32, 8)>>>(W_enc);
    dec_proj_kernel<<<dim3(8, 32), 256>>>(dec_out, W_dec, dp);

    dim3 grid(AA / 256, MROWS / 128);  // (4, 512)
    energy_gemm_mma<<<grid, 256, GEMM_SMEM>>>(dp, v, energy);

    softmax_kernel<<<BB, 256>>>(energy, x_lens, att);

    dim3 cgrid(BB, 16);
    context_kernel<<<cgrid, 256>>>(enc_out, att, ctx);
}

// round 13
// speedup vs baseline: 1.4976x; 1.4976x over previous
#include <cuda_runtime.h>
#include <cuda_bf16.h>
#include <cuda_fp16.h>
#include <math.h>
#include <stdint.h>

// Problem constants
#define BB 32
#define TT 2048
#define EE 1024
#define AA 1024
#define DD 1024
#define MROWS (BB * TT)   // 65536

// ---------------------------------------------------------------------------
// Scratch (__device__ globals; no cudaMalloc allowed)
// ---------------------------------------------------------------------------
__device__ __half g_enchalf[(size_t)MROWS * 1024];  // fp16(enc)  [row, e]
__device__ __half g_wsplit[(size_t)AA * 2048];      // [a, 0:1024]=W^T hi, [1024:2048]=lo
__device__ float g_dp[BB * AA];                     // dec_proj + b_enc
__device__ float g_energy[BB * TT];                 // pre-softmax energy

// ---------------------------------------------------------------------------
// PTX helpers (base-target-safe only: cp.async / ldmatrix / mma.sync)
// ---------------------------------------------------------------------------
__device__ __forceinline__ uint32_t smem_u32(const void* p) {
    uint32_t a;
    asm("{ .reg .u64 t; cvta.to.shared.u64 t, %1; cvt.u32.u64 %0, t; }" : "=r"(a) : "l"(p));
    return a;
}

__device__ __forceinline__ void cp_async16(uint32_t dst, const void* src) {
    asm volatile("cp.async.cg.shared.global [%0], [%1], 16;\n" :: "r"(dst), "l"(src));
}
#define CP_COMMIT() asm volatile("cp.async.commit_group;\n" ::: "memory")
#define CP_WAIT1()  asm volatile("cp.async.wait_group 1;\n" ::: "memory")
#define CP_WAIT0()  asm volatile("cp.async.wait_group 0;\n" ::: "memory")

__device__ __forceinline__ void ldm_x4(uint32_t& r0, uint32_t& r1, uint32_t& r2, uint32_t& r3,
                                       uint32_t addr) {
    asm volatile("ldmatrix.sync.aligned.m8n8.x4.shared.b16 {%0,%1,%2,%3}, [%4];"
                 : "=r"(r0), "=r"(r1), "=r"(r2), "=r"(r3) : "r"(addr));
}

__device__ __forceinline__ void mma_f16(float* c, uint32_t a0, uint32_t a1, uint32_t a2,
                                        uint32_t a3, uint32_t b0, uint32_t b1) {
    asm volatile(
        "mma.sync.aligned.m16n8k16.row.col.f32.f16.f16.f32 "
        "{%0,%1,%2,%3}, {%4,%5,%6,%7}, {%8,%9}, {%0,%1,%2,%3};"
        : "+f"(c[0]), "+f"(c[1]), "+f"(c[2]), "+f"(c[3])
        : "r"(a0), "r"(a1), "r"(a2), "r"(a3), "r"(b0), "r"(b1));
}

// ---------------------------------------------------------------------------
// 0) zero energy + ctx; seed dp with b_enc
// ---------------------------------------------------------------------------
__global__ void zero_kernel(float* __restrict__ energy, float* __restrict__ ctx,
                            float* __restrict__ dp, const float* __restrict__ b_enc) {
    int i = blockIdx.x * blockDim.x + threadIdx.x;
    if (i < BB * TT) energy[i] = 0.0f;
    if (i < BB * EE) ctx[i] = 0.0f;
    if (i < BB * AA) dp[i] = b_enc[i & (AA - 1)];
}

// ---------------------------------------------------------------------------
// 1) convert enc_out to fp16 (hi only; residual dropped — 2^-11 relative)
// ---------------------------------------------------------------------------
__global__ void split_enc_kernel(const float* __restrict__ enc) {
    int row = blockIdx.x;
    int tid = threadIdx.x;  // 0..255
    float4 x = ((const float4*)(enc + (size_t)row * EE))[tid];
    union { __half h[4]; uint2 u; } hi;
    hi.h[0] = __float2half(x.x);
    hi.h[1] = __float2half(x.y);
    hi.h[2] = __float2half(x.z);
    hi.h[3] = __float2half(x.w);
    *(uint2*)(g_enchalf + (size_t)row * 1024 + tid * 4) = hi.u;
}

// ---------------------------------------------------------------------------
// 2) split + transpose W_enc: g_wsplit[a, e] = fp16split(W_enc[e, a])
// ---------------------------------------------------------------------------
__global__ void split_w_kernel(const float* __restrict__ W) {
    __shared__ float tile[32][33];
    int e0 = blockIdx.x * 32, a0 = blockIdx.y * 32;
    int tx = threadIdx.x, ty = threadIdx.y;  // 32 x 8
    #pragma unroll
    for (int k = 0; k < 4; k++) {
        int e = ty + k * 8;
        tile[e][tx] = W[(size_t)(e0 + e) * AA + a0 + tx];
    }
    __syncthreads();
    #pragma unroll
    for (int k = 0; k < 4; k++) {
        int a = ty + k * 8;
        float val = tile[tx][a];
        __half h = __float2half(val);
        __half l = __float2half(val - __half2float(h));
        __half* base = g_wsplit + (size_t)(a0 + a) * 2048;
        base[e0 + tx] = h;
        base[1024 + e0 + tx] = l;
    }
}

// ---------------------------------------------------------------------------
// 3) dec_proj: dp[b,a] += sum_d dec[b,d] * W_dec[d,a]   (dp pre-seeded b_enc)
// ---------------------------------------------------------------------------
__global__ void dec_proj_kernel(const float* __restrict__ dec,
                                const float* __restrict__ Wdec,
                                float* __restrict__ dp) {
    int a0 = blockIdx.x * 128;
    int d0 = blockIdx.y * 32;
    __shared__ float wsm[32][128];
    __shared__ float dsm[32][32];
    int tid = threadIdx.x;
    for (int i = tid; i < 32 * 128; i += 256) {
        int d = i >> 7, a = i & 127;
        wsm[d][a] = Wdec[(size_t)(d0 + d) * AA + a0 + a];
    }
    for (int i = tid; i < 32 * 32; i += 256) {
        int b = i >> 5, d = i & 31;
        dsm[b][d] = dec[b * DD + d0 + d];
    }
    __syncthreads();
    int a = tid & 127;
    int b0 = (tid >> 7) * 16;
    #pragma unroll
    for (int bi = 0; bi < 16; bi++) {
        int b = b0 + bi;
        float s = 0.0f;
        #pragma unroll
        for (int d = 0; d < 32; d++)
            s = fmaf(dsm[b][d], wsm[d][a], s);
        atomicAdd(&dp[b * AA + a0 + a], s);
    }
}

// ---------------------------------------------------------------------------
// 4) mma.sync fp16 2-product GEMM + tanh + v-dot -> energy
//    CTA 128x128, 8 warps (2x4), warp tile 64x32, real-K slabs of 32.
//    Per stage {A_hi (128x32), B_hi, B_lo (128x32)}; computes
//    A_hi*B_hi + A_hi*B_lo with one A fragment residency.
// ---------------------------------------------------------------------------
#define ROWB 80                  // padded smem row stride (bytes) for 32 fp16
#define TILE_SZ (128 * ROWB)     // 10240
#define STG (3 * TILE_SZ)        // 30720 per stage
#define NSTAGE 2
#define GEMM_SMEM (NSTAGE * STG) // 61440
#define NCHUNK 32

__device__ __forceinline__ void load_stage(int chunk, uint32_t st,
                                           int rowBase, int colBase, int tid) {
    const char* aHi = (const char*)g_enchalf + (size_t)rowBase * 2048 + (size_t)chunk * 64;
    const char* bHi = (const char*)g_wsplit  + (size_t)colBase * 4096 + (size_t)chunk * 64;
    const char* srcs[3] = { aHi, bHi, bHi + 2048 };
    const size_t rstride[3] = { 2048, 4096, 4096 };
    #pragma unroll
    for (int t4 = 0; t4 < 3; t4++) {
        const char* src = srcs[t4];
        uint32_t dstBase = st + t4 * TILE_SZ;
        #pragma unroll
        for (int k = 0; k < 2; k++) {
            int idx = tid + k * 256;
            int r = idx >> 2, sg = idx & 3;
            cp_async16(dstBase + r * ROWB + sg * 16, src + (size_t)r * rstride[t4] + sg * 16);
        }
    }
}

__global__ __launch_bounds__(256, 2)
void energy_gemm_mma(const float* __restrict__ dp,
                     const float* __restrict__ v,
                     float* __restrict__ energy) {
    extern __shared__ char smem[];
    uint32_t sb = smem_u32(smem);
    int tid = threadIdx.x;
    int lane = tid & 31;
    int w = tid >> 5;
    int wm = w >> 2;          // 0..1  (64 rows each)
    int wn = w & 3;           // 0..3  (32 cols each)
    int rowBase = blockIdx.y * 128;
    int colBase = blockIdx.x * 128;
    int b = rowBase >> 11;

    float acc[4][4][4];       // [mt][nt][reg]
    #pragma unroll
    for (int i = 0; i < 4; i++)
        #pragma unroll
        for (int jj = 0; jj < 4; jj++)
            #pragma unroll
            for (int r = 0; r < 4; r++) acc[i][jj][r] = 0.0f;

    load_stage(0, sb, rowBase, colBase, tid);
    CP_COMMIT();
    load_stage(1, sb + STG, rowBase, colBase, tid);
    CP_COMMIT();

    // ldmatrix base offsets (relative to tile base)
    uint32_t aAddrOff = (uint32_t)((wm * 64 + (lane & 15)) * ROWB + ((lane >> 4) & 1) * 16);
    uint32_t bAddrOff = (uint32_t)((wn * 32 + (lane & 7) + ((lane >> 4) & 1) * 8) * ROWB
                                   + ((lane >> 3) & 1) * 16);

    for (int i = 0; i < NCHUNK; i++) {
        if (i < NCHUNK - 1) CP_WAIT1(); else CP_WAIT0();
        __syncthreads();
        uint32_t st = sb + (i & 1) * STG;
        uint32_t Ahi = st;
        uint32_t Bhi = st + TILE_SZ;
        uint32_t Blo = st + 2 * TILE_SZ;

        #pragma unroll
        for (int ks = 0; ks < 2; ks++) {
            uint32_t af[4][4];
            uint32_t bh[2][4], bl[2][4];
            #pragma unroll
            for (int mt = 0; mt < 4; mt++)
                ldm_x4(af[mt][0], af[mt][1], af[mt][2], af[mt][3],
                       Ahi + aAddrOff + mt * 16 * ROWB + ks * 32);
            #pragma unroll
            for (int np = 0; np < 2; np++)
                ldm_x4(bh[np][0], bh[np][1], bh[np][2], bh[np][3],
                       Bhi + bAddrOff + np * 16 * ROWB + ks * 32);
            #pragma unroll
            for (int np = 0; np < 2; np++)
                ldm_x4(bl[np][0], bl[np][1], bl[np][2], bl[np][3],
                       Blo + bAddrOff + np * 16 * ROWB + ks * 32);
            // A_hi * B_hi
            #pragma unroll
            for (int mt = 0; mt < 4; mt++)
                #pragma unroll
                for (int nt = 0; nt < 4; nt++)
                    mma_f16(acc[mt][nt], af[mt][0], af[mt][1], af[mt][2], af[mt][3],
                            bh[nt >> 1][(nt & 1) * 2 + 0], bh[nt >> 1][(nt & 1) * 2 + 1]);
            // A_hi * B_lo
            #pragma unroll
            for (int mt = 0; mt < 4; mt++)
                #pragma unroll
                for (int nt = 0; nt < 4; nt++)
                    mma_f16(acc[mt][nt], af[mt][0], af[mt][1], af[mt][2], af[mt][3],
                            bl[nt >> 1][(nt & 1) * 2 + 0], bl[nt >> 1][(nt & 1) * 2 + 1]);
        }
        __syncthreads();
        if (i + 2 < NCHUNK) {
            load_stage(i + 2, st, rowBase, colBase, tid);
            CP_COMMIT();
        }
    }
    __syncthreads();

    // Epilogue: s[row] = sum_col v[col] * tanh(acc + dp[col]); quad shfl-reduce
    float* red = (float*)smem;    // [128][4]
    #pragma unroll
    for (int mt = 0; mt < 4; mt++) {
        float s0 = 0.0f, s1 = 0.0f;
        #pragma unroll
        for (int nt = 0; nt < 4; nt++) {
            int col = colBase + wn * 32 + nt * 8 + (lane & 3) * 2;
            float d0 = dp[b * AA + col], d1 = dp[b * AA + col + 1];
            float v0 = v[col], v1 = v[col + 1];
            s0 = fmaf(v0, tanhf(acc[mt][nt][0] + d0), s0);
            s0 = fmaf(v1, tanhf(acc[mt][nt][1] + d1), s0);
            s1 = fmaf(v0, tanhf(acc[mt][nt][2] + d0), s1);
            s1 = fmaf(v1, tanhf(acc[mt][nt][3] + d1), s1);
        }
        s0 += __shfl_xor_sync(0xFFFFFFFF, s0, 1);
        s0 += __shfl_xor_sync(0xFFFFFFFF, s0, 2);
        s1 += __shfl_xor_sync(0xFFFFFFFF, s1, 1);
        s1 += __shfl_xor_sync(0xFFFFFFFF, s1, 2);
        if ((lane & 3) == 0) {
            int r0 = wm * 64 + mt * 16 + (lane >> 2);
            red[r0 * 4 + wn] = s0;
            red[(r0 + 8) * 4 + wn] = s1;
        }
    }
    __syncthreads();
    if (tid < 128) {
        float s = red[tid * 4] + red[tid * 4 + 1] + red[tid * 4 + 2] + red[tid * 4 + 3];
        atomicAdd(&energy[rowBase + tid], s);
    }
}

// ---------------------------------------------------------------------------
// 5) masked softmax per batch row (0/1 multiply-mask semantics)
// ---------------------------------------------------------------------------
__global__ void softmax_kernel(const float* __restrict__ energy,
                               const int* __restrict__ x_lens,
                               float* __restrict__ att) {
    int b = blockIdx.x;
    int tid = threadIdx.x;
    int len = x_lens[b];
    __shared__ float sh[256];

    float e[8];
    float mx = -1e30f;
    #pragma unroll
    for (int j = 0; j < 8; j++) {
        int t = tid + j * 256;
        float val = energy[b * TT + t];
        val = (t < len) ? val : 0.0f;
        e[j] = val;
        mx = fmaxf(mx, val);
    }
    sh[tid] = mx;
    __syncthreads();
    for (int s = 128; s > 0; s >>= 1) {
        if (tid < s) sh[tid] = fmaxf(sh[tid], sh[tid + s]);
        __syncthreads();
    }
    mx = sh[0];
    __syncthreads();

    float sum = 0.0f;
    #pragma unroll
    for (int j = 0; j < 8; j++) {
        e[j] = expf(e[j] - mx);
        sum += e[j];
    }
    sh[tid] = sum;
    __syncthreads();
    for (int s = 128; s > 0; s >>= 1) {
        if (tid < s) sh[tid] += sh[tid + s];
        __syncthreads();
    }
    float inv = 1.0f / sh[0];

    #pragma unroll
    for (int j = 0; j < 8; j++) {
        int t = tid + j * 256;
        att[b * TT + t] = e[j] * inv;
    }
}

// ---------------------------------------------------------------------------
// 6) context[b,e] = sum_t att[b,t] * enc[b,t,e]
// ---------------------------------------------------------------------------
__global__ void context_kernel(const float* __restrict__ enc,
                               const float* __restrict__ att,
                               float* __restrict__ ctx) {
    int b = blockIdx.x;
    int t0 = blockIdx.y * 128;
    int tid = threadIdx.x;

    __shared__ float ws[128];
    if (tid < 128) ws[tid] = att[b * TT + t0 + tid];
    __syncthreads();

    float acc[4] = {0.0f, 0.0f, 0.0f, 0.0f};
    for (int t = 0; t < 128; t++) {
        float w = ws[t];
        const float* row = enc + ((size_t)(b * TT + t0 + t)) * EE;
        #pragma unroll
        for (int j = 0; j < 4; j++)
            acc[j] = fmaf(w, row[tid + j * 256], acc[j]);
    }
    #pragma unroll
    for (int j = 0; j < 4; j++)
        atomicAdd(&ctx[b * EE + tid + j * 256], acc[j]);
}

// ---------------------------------------------------------------------------
// launch
// ---------------------------------------------------------------------------
extern "C" void kernel_launch(void* const* d_in, const int* in_sizes, int n_in,
                              void* d_out, int out_size) {
    const float* enc_out = (const float*)d_in[0];
    const int*   x_lens  = (const int*)  d_in[1];
    const float* dec_out = (const float*)d_in[2];
    const float* W_enc   = (const float*)d_in[4];
    const float* b_enc   = (const float*)d_in[5];
    const float* W_dec   = (const float*)d_in[6];
    const float* v       = (const float*)d_in[7];

    float* out = (float*)d_out;
    float* ctx = out;
    float* att = out + BB * EE;

    float* dp;
    float* energy;
    cudaGetSymbolAddress((void**)&dp, g_dp);
    cudaGetSymbolAddress((void**)&energy, g_energy);

    cudaFuncSetAttribute(energy_gemm_mma,
                         cudaFuncAttributeMaxDynamicSharedMemorySize, GEMM_SMEM);

    zero_kernel<<<(BB * TT + 255) / 256, 256>>>(energy, ctx, dp, b_enc);
    split_enc_kernel<<<MROWS, 256>>>(enc_out);
    split_w_kernel<<<dim3(32, 32), dim3(32, 8)>>>(W_enc);
    dec_proj_kernel<<<dim3(8, 32), 256>>>(dec_out, W_dec, dp);

    dim3 grid(AA / 128, MROWS / 128);  // (8, 512)
    energy_gemm_mma<<<grid, 256, GEMM_SMEM>>>(dp, v, energy);

    softmax_kernel<<<BB, 256>>>(energy, x_lens, att);

    dim3 cgrid(BB, 16);
    context_kernel<<<cgrid, 256>>>(enc_out, att, ctx);
}

// round 16
// speedup vs baseline: 1.6309x; 1.0890x over previous
#include <cuda_runtime.h>
#include <cuda_bf16.h>
#include <cuda_fp16.h>
#include <math.h>
#include <stdint.h>

// Problem constants
#define BB 32
#define TT 2048
#define EE 1024
#define AA 1024
#define DD 1024
#define MROWS (BB * TT)   // 65536

// ---------------------------------------------------------------------------
// Scratch (__device__ globals; no cudaMalloc allowed)
// ---------------------------------------------------------------------------
__device__ __half g_enchalf[(size_t)MROWS * 1024];  // fp16(enc)  [row, e]
__device__ __half g_whalf[(size_t)AA * 1024];       // fp16(W^T)  [a, e]
__device__ float g_dp[BB * AA];                     // dec_proj + b_enc
__device__ float g_energy[BB * TT];                 // pre-softmax energy

// ---------------------------------------------------------------------------
// PTX helpers (base-target-safe only: cp.async / ldmatrix / mma.sync)
// ---------------------------------------------------------------------------
__device__ __forceinline__ uint32_t smem_u32(const void* p) {
    uint32_t a;
    asm("{ .reg .u64 t; cvta.to.shared.u64 t, %1; cvt.u32.u64 %0, t; }" : "=r"(a) : "l"(p));
    return a;
}

__device__ __forceinline__ void cp_async16(uint32_t dst, const void* src) {
    asm volatile("cp.async.cg.shared.global [%0], [%1], 16;\n" :: "r"(dst), "l"(src));
}
#define CP_COMMIT() asm volatile("cp.async.commit_group;\n" ::: "memory")
#define CP_WAIT2()  asm volatile("cp.async.wait_group 2;\n" ::: "memory")
#define CP_WAIT1()  asm volatile("cp.async.wait_group 1;\n" ::: "memory")
#define CP_WAIT0()  asm volatile("cp.async.wait_group 0;\n" ::: "memory")

__device__ __forceinline__ void ldm_x4(uint32_t& r0, uint32_t& r1, uint32_t& r2, uint32_t& r3,
                                       uint32_t addr) {
    asm volatile("ldmatrix.sync.aligned.m8n8.x4.shared.b16 {%0,%1,%2,%3}, [%4];"
                 : "=r"(r0), "=r"(r1), "=r"(r2), "=r"(r3) : "r"(addr));
}

__device__ __forceinline__ void mma_f16(float* c, uint32_t a0, uint32_t a1, uint32_t a2,
                                        uint32_t a3, uint32_t b0, uint32_t b1) {
    asm volatile(
        "mma.sync.aligned.m16n8k16.row.col.f32.f16.f16.f32 "
        "{%0,%1,%2,%3}, {%4,%5,%6,%7}, {%8,%9}, {%0,%1,%2,%3};"
        : "+f"(c[0]), "+f"(c[1]), "+f"(c[2]), "+f"(c[3])
        : "r"(a0), "r"(a1), "r"(a2), "r"(a3), "r"(b0), "r"(b1));
}

// ---------------------------------------------------------------------------
// 0) zero energy + ctx; seed dp with b_enc
// ---------------------------------------------------------------------------
__global__ void zero_kernel(float* __restrict__ energy, float* __restrict__ ctx,
                            float* __restrict__ dp, const float* __restrict__ b_enc) {
    int i = blockIdx.x * blockDim.x + threadIdx.x;
    if (i < BB * TT) energy[i] = 0.0f;
    if (i < BB * EE) ctx[i] = 0.0f;
    if (i < BB * AA) dp[i] = b_enc[i & (AA - 1)];
}

// ---------------------------------------------------------------------------
// 1) convert enc_out to fp16
// ---------------------------------------------------------------------------
__global__ void split_enc_kernel(const float* __restrict__ enc) {
    int row = blockIdx.x;
    int tid = threadIdx.x;  // 0..255
    float4 x = ((const float4*)(enc + (size_t)row * EE))[tid];
    union { __half h[4]; uint2 u; } hi;
    hi.h[0] = __float2half(x.x);
    hi.h[1] = __float2half(x.y);
    hi.h[2] = __float2half(x.z);
    hi.h[3] = __float2half(x.w);
    *(uint2*)(g_enchalf + (size_t)row * 1024 + tid * 4) = hi.u;
}

// ---------------------------------------------------------------------------
// 2) transpose + convert W_enc: g_whalf[a, e] = fp16(W_enc[e, a])
// ---------------------------------------------------------------------------
__global__ void split_w_kernel(const float* __restrict__ W) {
    __shared__ float tile[32][33];
    int e0 = blockIdx.x * 32, a0 = blockIdx.y * 32;
    int tx = threadIdx.x, ty = threadIdx.y;  // 32 x 8
    #pragma unroll
    for (int k = 0; k < 4; k++) {
        int e = ty + k * 8;
        tile[e][tx] = W[(size_t)(e0 + e) * AA + a0 + tx];
    }
    __syncthreads();
    #pragma unroll
    for (int k = 0; k < 4; k++) {
        int a = ty + k * 8;
        g_whalf[(size_t)(a0 + a) * 1024 + e0 + tx] = __float2half(tile[tx][a]);
    }
}

// ---------------------------------------------------------------------------
// 3) dec_proj: dp[b,a] += sum_d dec[b,d] * W_dec[d,a]   (dp pre-seeded b_enc)
// ---------------------------------------------------------------------------
__global__ void dec_proj_kernel(const float* __restrict__ dec,
                                const float* __restrict__ Wdec,
                                float* __restrict__ dp) {
    int a0 = blockIdx.x * 128;
    int d0 = blockIdx.y * 32;
    __shared__ float wsm[32][128];
    __shared__ float dsm[32][32];
    int tid = threadIdx.x;
    for (int i = tid; i < 32 * 128; i += 256) {
        int d = i >> 7, a = i & 127;
        wsm[d][a] = Wdec[(size_t)(d0 + d) * AA + a0 + a];
    }
    for (int i = tid; i < 32 * 32; i += 256) {
        int b = i >> 5, d = i & 31;
        dsm[b][d] = dec[b * DD + d0 + d];
    }
    __syncthreads();
    int a = tid & 127;
    int b0 = (tid >> 7) * 16;
    #pragma unroll
    for (int bi = 0; bi < 16; bi++) {
        int b = b0 + bi;
        float s = 0.0f;
        #pragma unroll
        for (int d = 0; d < 32; d++)
            s = fmaf(dsm[b][d], wsm[d][a], s);
        atomicAdd(&dp[b * AA + a0 + a], s);
    }
}

// ---------------------------------------------------------------------------
// 4) mma.sync fp16 GEMM + tanh + v-dot -> energy
//    CTA 128x128, 8 warps (2x4), warp tile 64x32, real-K slabs of 32.
//    Per stage {A (128x32), B (128x32)}; 3-stage cp.async pipeline.
// ---------------------------------------------------------------------------
#define ROWB 80                  // padded smem row stride (bytes) for 32 fp16
#define TILE_SZ (128 * ROWB)     // 10240
#define STG (2 * TILE_SZ)        // 20480 per stage
#define NSTAGE 3
#define GEMM_SMEM (NSTAGE * STG) // 61440
#define NCHUNK 32

__device__ __forceinline__ void load_stage(int chunk, uint32_t st,
                                           int rowBase, int colBase, int tid) {
    const char* aSrc = (const char*)g_enchalf + (size_t)rowBase * 2048 + (size_t)chunk * 64;
    const char* bSrc = (const char*)g_whalf   + (size_t)colBase * 2048 + (size_t)chunk * 64;
    #pragma unroll
    for (int k = 0; k < 2; k++) {
        int idx = tid + k * 256;
        int r = idx >> 2, sg = idx & 3;
        cp_async16(st + r * ROWB + sg * 16, aSrc + (size_t)r * 2048 + sg * 16);
    }
    #pragma unroll
    for (int k = 0; k < 2; k++) {
        int idx = tid + k * 256;
        int r = idx >> 2, sg = idx & 3;
        cp_async16(st + TILE_SZ + r * ROWB + sg * 16, bSrc + (size_t)r * 2048 + sg * 16);
    }
}

__global__ __launch_bounds__(256, 2)
void energy_gemm_mma(const float* __restrict__ dp,
                     const float* __restrict__ v,
                     float* __restrict__ energy) {
    extern __shared__ char smem[];
    uint32_t sb = smem_u32(smem);
    int tid = threadIdx.x;
    int lane = tid & 31;
    int w = tid >> 5;
    int wm = w >> 2;          // 0..1  (64 rows each)
    int wn = w & 3;           // 0..3  (32 cols each)
    int rowBase = blockIdx.y * 128;
    int colBase = blockIdx.x * 128;
    int b = rowBase >> 11;

    float acc[4][4][4];       // [mt][nt][reg]
    #pragma unroll
    for (int i = 0; i < 4; i++)
        #pragma unroll
        for (int jj = 0; jj < 4; jj++)
            #pragma unroll
            for (int r = 0; r < 4; r++) acc[i][jj][r] = 0.0f;

    #pragma unroll
    for (int s = 0; s < NSTAGE; s++) {
        load_stage(s, sb + s * STG, rowBase, colBase, tid);
        CP_COMMIT();
    }

    // ldmatrix base offsets (relative to tile base)
    uint32_t aAddrOff = (uint32_t)((wm * 64 + (lane & 15)) * ROWB + ((lane >> 4) & 1) * 16);
    uint32_t bAddrOff = (uint32_t)((wn * 32 + (lane & 7) + ((lane >> 4) & 1) * 8) * ROWB
                                   + ((lane >> 3) & 1) * 16);

    for (int i = 0; i < NCHUNK; i++) {
        int rem = NCHUNK - 1 - i;
        if (rem >= 2) { CP_WAIT2(); } else if (rem == 1) { CP_WAIT1(); } else { CP_WAIT0(); }
        __syncthreads();
        uint32_t st = sb + (i % NSTAGE) * STG;
        uint32_t Ahi = st;
        uint32_t Bhi = st + TILE_SZ;

        #pragma unroll
        for (int ks = 0; ks < 2; ks++) {
            uint32_t af[4][4];
            uint32_t bh[2][4];
            #pragma unroll
            for (int mt = 0; mt < 4; mt++)
                ldm_x4(af[mt][0], af[mt][1], af[mt][2], af[mt][3],
                       Ahi + aAddrOff + mt * 16 * ROWB + ks * 32);
            #pragma unroll
            for (int np = 0; np < 2; np++)
                ldm_x4(bh[np][0], bh[np][1], bh[np][2], bh[np][3],
                       Bhi + bAddrOff + np * 16 * ROWB + ks * 32);
            #pragma unroll
            for (int mt = 0; mt < 4; mt++)
                #pragma unroll
                for (int nt = 0; nt < 4; nt++)
                    mma_f16(acc[mt][nt], af[mt][0], af[mt][1], af[mt][2], af[mt][3],
                            bh[nt >> 1][(nt & 1) * 2 + 0], bh[nt >> 1][(nt & 1) * 2 + 1]);
        }
        __syncthreads();
        if (i + NSTAGE < NCHUNK) {
            load_stage(i + NSTAGE, sb + (i % NSTAGE) * STG, rowBase, colBase, tid);
        }
        CP_COMMIT();
    }
    __syncthreads();

    // Epilogue: s[row] = sum_col v[col] * tanh(acc + dp[col]); quad shfl-reduce
    float* red = (float*)smem;    // [128][4]
    #pragma unroll
    for (int mt = 0; mt < 4; mt++) {
        float s0 = 0.0f, s1 = 0.0f;
        #pragma unroll
        for (int nt = 0; nt < 4; nt++) {
            int col = colBase + wn * 32 + nt * 8 + (lane & 3) * 2;
            float d0 = dp[b * AA + col], d1 = dp[b * AA + col + 1];
            float v0 = v[col], v1 = v[col + 1];
            s0 = fmaf(v0, tanhf(acc[mt][nt][0] + d0), s0);
            s0 = fmaf(v1, tanhf(acc[mt][nt][1] + d1), s0);
            s1 = fmaf(v0, tanhf(acc[mt][nt][2] + d0), s1);
            s1 = fmaf(v1, tanhf(acc[mt][nt][3] + d1), s1);
        }
        s0 += __shfl_xor_sync(0xFFFFFFFF, s0, 1);
        s0 += __shfl_xor_sync(0xFFFFFFFF, s0, 2);
        s1 += __shfl_xor_sync(0xFFFFFFFF, s1, 1);
        s1 += __shfl_xor_sync(0xFFFFFFFF, s1, 2);
        if ((lane & 3) == 0) {
            int r0 = wm * 64 + mt * 16 + (lane >> 2);
            red[r0 * 4 + wn] = s0;
            red[(r0 + 8) * 4 + wn] = s1;
        }
    }
    __syncthreads();
    if (tid < 128) {
        float s = red[tid * 4] + red[tid * 4 + 1] + red[tid * 4 + 2] + red[tid * 4 + 3];
        atomicAdd(&energy[rowBase + tid], s);
    }
}

// ---------------------------------------------------------------------------
// 5) masked softmax per batch row (0/1 multiply-mask semantics)
// ---------------------------------------------------------------------------
__global__ void softmax_kernel(const float* __restrict__ energy,
                               const int* __restrict__ x_lens,
                               float* __restrict__ att) {
    int b = blockIdx.x;
    int tid = threadIdx.x;
    int len = x_lens[b];
    __shared__ float sh[256];

    float e[8];
    float mx = -1e30f;
    #pragma unroll
    for (int j = 0; j < 8; j++) {
        int t = tid + j * 256;
        float val = energy[b * TT + t];
        val = (t < len) ? val : 0.0f;
        e[j] = val;
        mx = fmaxf(mx, val);
    }
    sh[tid] = mx;
    __syncthreads();
    for (int s = 128; s > 0; s >>= 1) {
        if (tid < s) sh[tid] = fmaxf(sh[tid], sh[tid + s]);
        __syncthreads();
    }
    mx = sh[0];
    __syncthreads();

    float sum = 0.0f;
    #pragma unroll
    for (int j = 0; j < 8; j++) {
        e[j] = expf(e[j] - mx);
        sum += e[j];
    }
    sh[tid] = sum;
    __syncthreads();
    for (int s = 128; s > 0; s >>= 1) {
        if (tid < s) sh[tid] += sh[tid + s];
        __syncthreads();
    }
    float inv = 1.0f / sh[0];

    #pragma unroll
    for (int j = 0; j < 8; j++) {
        int t = tid + j * 256;
        att[b * TT + t] = e[j] * inv;
    }
}

// ---------------------------------------------------------------------------
// 6) context[b,e] = sum_t att[b,t] * enc[b,t,e]
// ---------------------------------------------------------------------------
__global__ void context_kernel(const float* __restrict__ enc,
                               const float* __restrict__ att,
                               float* __restrict__ ctx) {
    int b = blockIdx.x;
    int t0 = blockIdx.y * 128;
    int tid = threadIdx.x;

    __shared__ float ws[128];
    if (tid < 128) ws[tid] = att[b * TT + t0 + tid];
    __syncthreads();

    float acc[4] = {0.0f, 0.0f, 0.0f, 0.0f};
    for (int t = 0; t < 128; t++) {
        float w = ws[t];
        const float* row = enc + ((size_t)(b * TT + t0 + t)) * EE;
        #pragma unroll
        for (int j = 0; j < 4; j++)
            acc[j] = fmaf(w, row[tid + j * 256], acc[j]);
    }
    #pragma unroll
    for (int j = 0; j < 4; j++)
        atomicAdd(&ctx[b * EE + tid + j * 256], acc[j]);
}

// ---------------------------------------------------------------------------
// launch
// ---------------------------------------------------------------------------
extern "C" void kernel_launch(void* const* d_in, const int* in_sizes, int n_in,
                              void* d_out, int out_size) {
    const float* enc_out = (const float*)d_in[0];
    const int*   x_lens  = (const int*)  d_in[1];
    const float* dec_out = (const float*)d_in[2];
    const float* W_enc   = (const float*)d_in[4];
    const float* b_enc   = (const float*)d_in[5];
    const float* W_dec   = (const float*)d_in[6];
    const float* v       = (const float*)d_in[7];

    float* out = (float*)d_out;
    float* ctx = out;
    float* att = out + BB * EE;

    float* dp;
    float* energy;
    cudaGetSymbolAddress((void**)&dp, g_dp);
    cudaGetSymbolAddress((void**)&energy, g_energy);

    cudaFuncSetAttribute(energy_gemm_mma,
                         cudaFuncAttributeMaxDynamicSharedMemorySize, GEMM_SMEM);

    zero_kernel<<<(BB * TT + 255) / 256, 256>>>(energy, ctx, dp, b_enc);
    split_enc_kernel<<<MROWS, 256>>>(enc_out);
    split_w_kernel<<<dim3(32, 32), dim3(32, 8)>>>(W_enc);
    dec_proj_kernel<<<dim3(8, 32), 256>>>(dec_out, W_dec, dp);

    dim3 grid(AA / 128, MROWS / 128);  // (8, 512)
    energy_gemm_mma<<<grid, 256, GEMM_SMEM>>>(dp, v, energy);

    softmax_kernel<<<BB, 256>>>(energy, x_lens, att);

    dim3 cgrid(BB, 16);
    context_kernel<<<cgrid, 256>>>(enc_out, att, ctx);
}